// round 11
// baseline (speedup 1.0000x reference)
#include <cuda_runtime.h>
#include <cuda_bf16.h>
#include <cstdint>

// Net_60413009985719 on GB300 (sm_103a).
//
// Algebraic collapse: `_lstm_step` zeroes h_prev INSIDE the step (no
// recurrence) and the head consumes only row L-1 -> whole net = scalar x[L-1]
// through 5 LSTM cells + tiny MLP head. f-gate rows are dead code.
//
// R8 change (single, for attribution): head-weight staging converted from
// LDG->STS (register-consuming, serialized the entire L1tex queue onto the
// first __syncthreads) to cp.async (LDGSTS, no register consumer). Entry loads
// reordered to L1tex-queue priority: layer0 scalars -> wA -> biases -> wB ->
// cp.async staging. Completion awaited only after layer 4.

#define H 64
#define G 256
#define T 384
#define NROW 192        // live gate rows per layer (i,g,o)

#define CP_ASYNC16(dst, src) \
    asm volatile("cp.async.ca.shared.global [%0], [%1], 16;" :: "r"(dst), "l"(src))
#define CP_ASYNC4(dst, src) \
    asm volatile("cp.async.ca.shared.global [%0], [%1], 4;" :: "r"(dst), "l"(src))

__device__ __forceinline__ float fsigm(float x) {
    return __fdividef(1.0f, 1.0f + __expf(-x));
}
__device__ __forceinline__ float ftanh(float x) {
    float e = __expf(2.0f * x);           // 0 / inf at extremes -> exact +-1
    return 1.0f - __fdividef(2.0f, e + 1.0f);
}
__device__ __forceinline__ float lstm_h(float gi, float gg, float go) {
    float c = fsigm(gi) * ftanh(gg);
    return fsigm(go) * ftanh(c);
}

__global__ __launch_bounds__(T, 1)
void net_kernel(const float* __restrict__ x, int L,
                const float* __restrict__ Wih0,   // (256,1)
                const float* __restrict__ bih0,   // (256,)
                const float* __restrict__ bhh0,   // (256,)
                const float* __restrict__ Wih,    // (4,256,64)
                const float* __restrict__ bih,    // (4,256)
                const float* __restrict__ bhh,    // (4,256)
                const float* __restrict__ fc_w,   // (32,64)
                const float* __restrict__ fc_b,   // (32,)
                const float* __restrict__ mean_w, // (1,32)
                const float* __restrict__ mean_b, // (1,)
                const float* __restrict__ ls_w,   // (1,32)
                const float* __restrict__ ls_b,   // (1,)
                const float* __restrict__ c1_w,   // (16,32)
                const float* __restrict__ c1_b,   // (16,)
                const float* __restrict__ c2_w,   // (1,16)
                const float* __restrict__ c2_b,   // (1,)
                float* __restrict__ out)          // [mean, log_std, v]
{
    __shared__ float sg[NROW];       // live gates: [i(64) | g(64) | o(64)]
    __shared__ float h[H];
    __shared__ float zs[32];
    __shared__ float c1s[16];
    __shared__ float sfc[32 * H];    // fc_w  (cp.async staged)
    __shared__ float sc1[16 * 32];   // c1_w  (cp.async staged)
    __shared__ float sfcb[32], sc1b[16];
    __shared__ float smw[32], ssw[32], scw[16];
    __shared__ float sconst[3];      // mean_b, ls_b, c2_b

    const int t    = threadIdx.x;      // 0..383
    const int tt   = t >> 1;           // live-row index 0..191
    const int half = t & 1;            // which 32-wide half of the dot
    const int type = tt >> 6;          // 0=i, 1=g, 2=o
    const int jrow = tt & 63;          // j within gate type
    // physical gate row in the (256,·) weight layout: i->j, g->128+j, o->192+j
    const int row  = jrow + ((type == 0) ? 0 : (type + 1) * H);

    // ------ entry loads, ordered by L1tex-queue priority ------
    // (1) layer-0 scalars: gate the first barrier via the h-threads.
    const float xv = x[L - 1];
    float w0i = 0.f, w0g = 0.f, w0o = 0.f, b0i = 0.f, b0g = 0.f, b0o = 0.f;
    if (t < H) {
        w0i = Wih0[t];           b0i = bih0[t]           + bhh0[t];
        w0g = Wih0[2 * H + t];   b0g = bih0[2 * H + t]   + bhh0[2 * H + t];
        w0o = Wih0[3 * H + t];   b0o = bih0[3 * H + t]   + bhh0[3 * H + t];
    }

    // (2) layer-1 weights (consumed first after the barrier).
    const float4* __restrict__ Wv = reinterpret_cast<const float4*>(Wih);
    const size_t base = (size_t)row * (H / 4) + (size_t)half * 8;
    const size_t lstride = (size_t)G * (H / 4);
    float4 wA[8], wB[8];
    #pragma unroll
    for (int i = 0; i < 8; i++) wA[i] = Wv[base + i];             // layer 1

    // (3) per-layer biases (consumed at the end of each dot).
    float bias[4];
    #pragma unroll
    for (int l = 0; l < 4; l++) bias[l] = bih[l * G + row] + bhh[l * G + row];

    // (4) layer-2 weights.
    #pragma unroll
    for (int i = 0; i < 8; i++) wB[i] = Wv[lstride + base + i];   // layer 2

    // (5) head staging via cp.async: NO register consumer, so warps reach the
    //     first barrier without waiting on these. Awaited after layer 4.
    {
        uint32_t s_sfc = (uint32_t)__cvta_generic_to_shared(sfc);
        uint32_t s_sc1 = (uint32_t)__cvta_generic_to_shared(sc1);
        CP_ASYNC16(s_sfc + t * 16, (const char*)fc_w + t * 16);        // 384 of 512
        if (t < 128)
            CP_ASYNC16(s_sfc + (384 + t) * 16, (const char*)fc_w + (384 + t) * 16);
        if (t >= 128 && t < 256)
            CP_ASYNC16(s_sc1 + (t - 128) * 16, (const char*)c1_w + (t - 128) * 16);
        int t2 = t - 256;                        // threads 256..383 for tails
        if (t2 >= 0 && t2 < 32)
            CP_ASYNC4((uint32_t)__cvta_generic_to_shared(sfcb + t2), fc_b + t2);
        else if (t2 >= 32 && t2 < 64)
            CP_ASYNC4((uint32_t)__cvta_generic_to_shared(smw + (t2 - 32)), mean_w + (t2 - 32));
        else if (t2 >= 64 && t2 < 96)
            CP_ASYNC4((uint32_t)__cvta_generic_to_shared(ssw + (t2 - 64)), ls_w + (t2 - 64));
        else if (t2 >= 96 && t2 < 112)
            CP_ASYNC4((uint32_t)__cvta_generic_to_shared(sc1b + (t2 - 96)), c1_b + (t2 - 96));
        else if (t2 >= 112 && t2 < 128)
            CP_ASYNC4((uint32_t)__cvta_generic_to_shared(scw + (t2 - 112)), c2_w + (t2 - 112));
        if (t == 383) {
            uint32_t s_sc = (uint32_t)__cvta_generic_to_shared(sconst);
            CP_ASYNC4(s_sc + 0, mean_b);
            CP_ASYNC4(s_sc + 4, ls_b);
            CP_ASYNC4(s_sc + 8, c2_b);
        }
        asm volatile("cp.async.commit_group;");
    }

    // ---------------- layer 0: computed locally by the h-threads ----------------
    if (t < H) {
        float gi = fmaf(xv, w0i, b0i);
        float gg = fmaf(xv, w0g, b0g);
        float go = fmaf(xv, w0o, b0o);
        h[t] = lstm_h(gi, gg, go);
    }
    __syncthreads();

    // ---------------- layers 1..4 ----------------
    // Prefetch of layer l+1 is issued FIRST (independent of h), then the
    // current layer's 32-MAC half-dot, pair-combined via shfl.
#define DOT_LAYER(buf, lcur, DO_PREF, lnext, nbuf)                             \
    {                                                                          \
        if (DO_PREF) {                                                         \
            _Pragma("unroll")                                                  \
            for (int i = 0; i < 8; i++)                                        \
                nbuf[i] = Wv[(size_t)(lnext) * lstride + base + i];            \
        }                                                                      \
        const float* __restrict__ hh = h + half * 32;                          \
        float a0 = 0.f, a1 = 0.f, a2 = 0.f, a3 = 0.f;                          \
        _Pragma("unroll")                                                      \
        for (int i = 0; i < 8; i++) {                                          \
            float4 w = buf[i];                                                 \
            int k = i * 4;                                                     \
            a0 = fmaf(w.x, hh[k + 0], a0);                                     \
            a1 = fmaf(w.y, hh[k + 1], a1);                                     \
            a2 = fmaf(w.z, hh[k + 2], a2);                                     \
            a3 = fmaf(w.w, hh[k + 3], a3);                                     \
        }                                                                      \
        float p = (a0 + a1) + (a2 + a3);                                       \
        p += __shfl_xor_sync(0xffffffffu, p, 1);                               \
        if (!half) sg[tt] = p + bias[lcur];                                    \
        __syncthreads();                                                       \
        if (t < H) h[t] = lstm_h(sg[t], sg[H + t], sg[2 * H + t]);             \
        __syncthreads();                                                       \
    }

    DOT_LAYER(wA, 0, 1, 2, wA);   // consume W[0]; W[2] load in flight -> wA
    DOT_LAYER(wB, 1, 1, 3, wB);   // consume W[1]; W[3] load in flight -> wB
    DOT_LAYER(wA, 2, 0, 0, wA);
    DOT_LAYER(wB, 3, 0, 0, wB);
#undef DOT_LAYER

    // Staging copies finished long ago; make them visible to all threads.
    asm volatile("cp.async.wait_group 0;");
    __syncthreads();

    // ---------------- head: entirely in warp 0 ----------------
    if (t < 32) {
        const float* __restrict__ W = sfc + t * H;
        float a0 = sfcb[t], a1 = 0.f, a2 = 0.f, a3 = 0.f;
        #pragma unroll
        for (int k = 0; k < H; k += 4) {
            a0 = fmaf(W[k + 0], h[k + 0], a0);
            a1 = fmaf(W[k + 1], h[k + 1], a1);
            a2 = fmaf(W[k + 2], h[k + 2], a2);
            a3 = fmaf(W[k + 3], h[k + 3], a3);
        }
        zs[t] = fmaxf((a0 + a1) + (a2 + a3), 0.0f);
        __syncwarp();

        if (t < 16) {                       // c1 layer
            const float* __restrict__ C = sc1 + t * 32;
            float b0_ = sc1b[t], b1_ = 0.f;
            #pragma unroll
            for (int k = 0; k < 32; k += 2) {
                b0_ = fmaf(C[k + 0], zs[k + 0], b0_);
                b1_ = fmaf(C[k + 1], zs[k + 1], b1_);
            }
            c1s[t] = fmaxf(b0_ + b1_, 0.0f);
        } else if (t == 16) {               // mean (concurrent with c1)
            float m0 = sconst[0], m1 = 0.f;
            #pragma unroll
            for (int k = 0; k < 32; k += 2) {
                m0 = fmaf(smw[k + 0], zs[k + 0], m0);
                m1 = fmaf(smw[k + 1], zs[k + 1], m1);
            }
            out[0] = m0 + m1;
        } else if (t == 17) {               // log_std (concurrent with c1)
            float s0 = sconst[1], s1 = 0.f;
            #pragma unroll
            for (int k = 0; k < 32; k += 2) {
                s0 = fmaf(ssw[k + 0], zs[k + 0], s0);
                s1 = fmaf(ssw[k + 1], zs[k + 1], s1);
            }
            out[1] = s0 + s1;
        }
        __syncwarp();

        if (t == 0) {                       // v
            float v0 = sconst[2], v1 = 0.f;
            #pragma unroll
            for (int k = 0; k < 16; k += 2) {
                v0 = fmaf(scw[k + 0], c1s[k + 0], v0);
                v1 = fmaf(scw[k + 1], c1s[k + 1], v1);
            }
            out[2] = v0 + v1;
        }
    }
}

extern "C" void kernel_launch(void* const* d_in, const int* in_sizes, int n_in,
                              void* d_out, int out_size)
{
    // metadata order:
    // 0:x 1:Wih0 2:Whh0 3:bih0 4:bhh0 5:Wih 6:Whh 7:bih 8:bhh
    // 9:fc_w 10:fc_b 11:mean_w 12:mean_b 13:ls_w 14:ls_b
    // 15:c1_w 16:c1_b 17:c2_w 18:c2_b
    const float* x      = (const float*)d_in[0];
    const float* Wih0   = (const float*)d_in[1];
    const float* bih0   = (const float*)d_in[3];
    const float* bhh0   = (const float*)d_in[4];
    const float* Wih    = (const float*)d_in[5];
    const float* bih    = (const float*)d_in[7];
    const float* bhh    = (const float*)d_in[8];
    const float* fc_w   = (const float*)d_in[9];
    const float* fc_b   = (const float*)d_in[10];
    const float* mean_w = (const float*)d_in[11];
    const float* mean_b = (const float*)d_in[12];
    const float* ls_w   = (const float*)d_in[13];
    const float* ls_b   = (const float*)d_in[14];
    const float* c1_w   = (const float*)d_in[15];
    const float* c1_b   = (const float*)d_in[16];
    const float* c2_w   = (const float*)d_in[17];
    const float* c2_b   = (const float*)d_in[18];
    const int L = in_sizes[0];

    net_kernel<<<1, T>>>(x, L, Wih0, bih0, bhh0, Wih, bih, bhh,
                         fc_w, fc_b, mean_w, mean_b, ls_w, ls_b,
                         c1_w, c1_b, c2_w, c2_b, (float*)d_out);
}